// round 3
// baseline (speedup 1.0000x reference)
#include <cuda_runtime.h>
#include <math.h>

#define B_ 16
#define N_ 64
#define E_ 512
#define C_ 512
#define H1_ 256
#define H2_ 128
#define H3_ 64
#define U_ 8
#define R_ 8
#define EH_ 64
#define EPS_ 1e-5f
#define NODE_OUT (B_*N_*N_*U_)   /* 524288 */

__device__ __align__(16) float g_x1[B_*N_*H1_];
__device__ __align__(16) float g_x2[B_*N_*H2_];
__device__ __align__(16) float g_x3[B_*N_*H3_];
__device__ __align__(16) float g_nodec[B_*N_*U_];
__device__ __align__(16) float g_P[B_*N_*EH_];
__device__ __align__(16) float g_Q[B_*N_*EH_];
__device__ __align__(16) float g_rel[B_*N_*N_*R_];
__device__ int g_see[B_*N_*N_];
__device__ int g_cnt[B_*N_];

// ---------------------------------------------------------------------------
// 1. Build see-table + counts. One block per batch, one thread per dst node.
// ---------------------------------------------------------------------------
__global__ void __launch_bounds__(64)
build_see_kernel(const int* __restrict__ edge_index) {
    __shared__ int sdst[E_];
    __shared__ int ssrc[E_];
    int b = blockIdx.x, n = threadIdx.x;
    const int* src = edge_index + b * 2 * E_;
    const int* dst = src + E_;
    for (int l = n; l < E_; l += 64) { ssrc[l] = src[l]; sdst[l] = dst[l]; }
    __syncthreads();
    int* row = g_see + (b * N_ + n) * N_;
    #pragma unroll 8
    for (int j = 0; j < N_; j++) row[j] = 0;
    row[0] = n;
    int c = 0;
    #pragma unroll 8
    for (int e = 0; e < E_; e++) {
        if (sdst[e] == n) {
            c++;
            if (c < N_) row[c] = ssrc[e];   // pos >= N dropped (mode='drop')
        }
    }
    g_cnt[b * N_ + n] = min(c + 1, N_);
}

// ---------------------------------------------------------------------------
// 2. Register-tiled SGEMM with fused epilogue.
//    EPI 0: relu(BN(x@W + bias));  EPI 1: relu(x@W + bias)
// ---------------------------------------------------------------------------
template<int BM, int BN, int EPI>
__global__ void __launch_bounds__((BM/4)*(BN/4))
gemm_kernel(const float* __restrict__ A, const float* __restrict__ W,
            float* __restrict__ C, int M, int Nc, int K,
            const float* __restrict__ bias,
            const float* __restrict__ gam, const float* __restrict__ bet,
            const float* __restrict__ mu,  const float* __restrict__ var)
{
    const int BK = 16;
    const int NTHR = (BM/4)*(BN/4);
    __shared__ __align__(16) float As[BK * (BM + 4)];
    __shared__ __align__(16) float Bs[BK * BN];
    int tid = threadIdx.x;
    int tc = tid % (BN/4);
    int tr = tid / (BN/4);
    int bm = blockIdx.y * BM;
    int bn = blockIdx.x * BN;
    float acc[4][4] = {};
    for (int k0 = 0; k0 < K; k0 += BK) {
        #pragma unroll
        for (int l = tid; l < BM*BK/4; l += NTHR) {
            int m  = l / (BK/4);
            int kk = (l % (BK/4)) * 4;
            float4 v = *reinterpret_cast<const float4*>(&A[(size_t)(bm+m)*K + k0 + kk]);
            As[(kk+0)*(BM+4)+m] = v.x;
            As[(kk+1)*(BM+4)+m] = v.y;
            As[(kk+2)*(BM+4)+m] = v.z;
            As[(kk+3)*(BM+4)+m] = v.w;
        }
        #pragma unroll
        for (int l = tid; l < BK*BN/4; l += NTHR) {
            int k  = l / (BN/4);
            int nn = (l % (BN/4)) * 4;
            *reinterpret_cast<float4*>(&Bs[k*BN+nn]) =
                *reinterpret_cast<const float4*>(&W[(size_t)(k0+k)*Nc + bn + nn]);
        }
        __syncthreads();
        #pragma unroll
        for (int k = 0; k < BK; k++) {
            float4 av = *reinterpret_cast<const float4*>(&As[k*(BM+4) + tr*4]);
            float4 bv = *reinterpret_cast<const float4*>(&Bs[k*BN + tc*4]);
            float a[4] = {av.x, av.y, av.z, av.w};
            float w[4] = {bv.x, bv.y, bv.z, bv.w};
            #pragma unroll
            for (int i = 0; i < 4; i++)
                #pragma unroll
                for (int j = 0; j < 4; j++)
                    acc[i][j] = fmaf(a[i], w[j], acc[i][j]);
        }
        __syncthreads();
    }
    #pragma unroll
    for (int i = 0; i < 4; i++) {
        int m = bm + tr*4 + i;
        float4 o;
        float* op = &o.x;
        #pragma unroll
        for (int j = 0; j < 4; j++) {
            int n = bn + tc*4 + j;
            float v = acc[i][j] + bias[n];
            if (EPI == 0) {
                float sc = gam[n] * rsqrtf(var[n] + EPS_);
                v = (v - mu[n]) * sc + bet[n];
            }
            op[j] = fmaxf(v, 0.0f);
        }
        *reinterpret_cast<float4*>(&C[(size_t)m*Nc + bn + tc*4]) = o;
    }
}

// ---------------------------------------------------------------------------
// 3. Node head: node_c = sigmoid(x3 @ wn + bn_c)   (1024 x 8, K=64)
// ---------------------------------------------------------------------------
__global__ void node_head_kernel(const float* __restrict__ wn,
                                 const float* __restrict__ bn_c) {
    int gid = blockIdx.x * blockDim.x + threadIdx.x;  // B*N*U = 8192
    if (gid >= B_*N_*U_) return;
    int row = gid >> 3, u = gid & 7;
    const float* xr = g_x3 + row * H3_;
    float s = bn_c[u];
    #pragma unroll 8
    for (int k = 0; k < H3_; k++) s = fmaf(xr[k], wn[k*U_ + u], s);
    g_nodec[gid] = 1.0f / (1.0f + expf(-s));
}

// ---------------------------------------------------------------------------
// 4. Edge layer-1 factorization: P = attr@we1[:9] + be1,  Q = attr@we1[9:]
// ---------------------------------------------------------------------------
__global__ void edge_pq_kernel(const float* __restrict__ bbox,
                               const float* __restrict__ dir,
                               const float* __restrict__ prio,
                               const float* __restrict__ we1,
                               const float* __restrict__ be1) {
    int gid = blockIdx.x * blockDim.x + threadIdx.x;  // B*N*EH = 65536
    if (gid >= B_*N_*EH_) return;
    int row = gid >> 6, h = gid & 63;
    const float inv = 1.0f / 1024.0f;
    float a[9];
    #pragma unroll
    for (int c = 0; c < 4; c++) a[c]   = bbox[row*4+c] * inv;
    #pragma unroll
    for (int c = 0; c < 4; c++) a[4+c] = dir[row*4+c];
    a[8] = prio[row];
    float p = be1[h], q = 0.0f;
    #pragma unroll
    for (int c = 0; c < 9; c++) {
        p = fmaf(a[c], we1[c*EH_ + h], p);
        q = fmaf(a[c], we1[(9+c)*EH_ + h], q);
    }
    g_P[gid] = p;
    g_Q[gid] = q;
}

// ---------------------------------------------------------------------------
// 5. Fused edge MLP: per (b,i) block compute e1 (smem) -> e2 (regs/smem) ->
//    rel[b,i,:,:] = sigmoid(e2 @ wei + bei). 1024 blocks x 256 threads.
// ---------------------------------------------------------------------------
__global__ void __launch_bounds__(256)
edge_fused_kernel(const float* __restrict__ we2, const float* __restrict__ be2,
                  const float* __restrict__ wei, const float* __restrict__ bei) {
    const int LD = 68;
    __shared__ __align__(16) float sE1[64*LD];   // phase 1: [h][j]; phase 2 reused as e2 [j][o]
    __shared__ __align__(16) float sW2[64*LD];   // [h][o]
    __shared__ float sP[64], sBe2[64], sWei[64*8], sBei[8];
    int tid = threadIdx.x;
    int bi = blockIdx.x;          // b*64 + i
    int b = bi >> 6;

    if (tid < 64) { sP[tid] = g_P[bi*64 + tid]; sBe2[tid] = be2[tid]; }
    if (tid < 8) sBei[tid] = bei[tid];
    for (int l = tid; l < 512; l += 256) sWei[l] = wei[l];
    for (int l = tid; l < 1024; l += 256) {
        float4 v = reinterpret_cast<const float4*>(we2)[l];
        int h = l >> 4, o = (l & 15) * 4;
        *reinterpret_cast<float4*>(&sW2[h*LD + o]) = v;
    }
    __syncthreads();

    // e1[h][j] = relu(P[b,i,h] + Q[b,j,h])
    const float4* Qb = reinterpret_cast<const float4*>(g_Q + b * N_ * EH_);
    for (int l = tid; l < 1024; l += 256) {
        float4 qv = Qb[l];
        int j = l >> 4, h0 = (l & 15) * 4;
        sE1[(h0+0)*LD + j] = fmaxf(sP[h0+0] + qv.x, 0.0f);
        sE1[(h0+1)*LD + j] = fmaxf(sP[h0+1] + qv.y, 0.0f);
        sE1[(h0+2)*LD + j] = fmaxf(sP[h0+2] + qv.z, 0.0f);
        sE1[(h0+3)*LD + j] = fmaxf(sP[h0+3] + qv.w, 0.0f);
    }
    __syncthreads();

    // e2[j][o] = relu(sum_h e1[j][h] * we2[h][o] + be2[o]); 4x4 per thread
    int tc = tid & 15, tr = tid >> 4;
    float acc[4][4] = {};
    #pragma unroll
    for (int h = 0; h < 64; h++) {
        float4 av = *reinterpret_cast<const float4*>(&sE1[h*LD + tr*4]);
        float4 bv = *reinterpret_cast<const float4*>(&sW2[h*LD + tc*4]);
        float a[4] = {av.x, av.y, av.z, av.w};
        float w[4] = {bv.x, bv.y, bv.z, bv.w};
        #pragma unroll
        for (int i = 0; i < 4; i++)
            #pragma unroll
            for (int j = 0; j < 4; j++)
                acc[i][j] = fmaf(a[i], w[j], acc[i][j]);
    }
    __syncthreads();   // everyone done reading e1 before overwrite
    #pragma unroll
    for (int i = 0; i < 4; i++)
        #pragma unroll
        for (int c = 0; c < 4; c++)
            sE1[(tr*4+i)*LD + tc*4 + c] = fmaxf(acc[i][c] + sBe2[tc*4+c], 0.0f);
    __syncthreads();

    // rel[j][r] = sigmoid(sum_o e2[j][o]*wei[o][r] + bei[r]); thread -> (j, 2 r's)
    int j = tid >> 2, r2 = tid & 3;
    float a0 = sBei[r2*2], a1 = sBei[r2*2+1];
    #pragma unroll 16
    for (int o = 0; o < 64; o++) {
        float e = sE1[j*LD + o];
        a0 = fmaf(e, sWei[o*8 + r2*2],     a0);
        a1 = fmaf(e, sWei[o*8 + r2*2 + 1], a1);
    }
    float2 out;
    out.x = 1.0f / (1.0f + expf(-a0));
    out.y = 1.0f / (1.0f + expf(-a1));
    *reinterpret_cast<float2*>(&g_rel[(bi*64 + j)*8 + r2*2]) = out;
}

// ---------------------------------------------------------------------------
// 6. node_concepts gather (writes first 524288 floats of out)
// ---------------------------------------------------------------------------
__global__ void node_gather_kernel(float* __restrict__ out) {
    int gid = blockIdx.x * blockDim.x + threadIdx.x;  // B*N*N = 65536
    if (gid >= B_*N_*N_) return;
    int j  = gid & 63;
    int bi = gid >> 6;
    int b  = gid >> 12;
    int s  = g_see[gid];
    float msk = (j < g_cnt[bi]) ? 1.0f : 0.0f;
    const float4* np = reinterpret_cast<const float4*>(g_nodec + (b*N_ + s)*U_);
    float4 v0 = np[0], v1 = np[1];
    v0.x *= msk; v0.y *= msk; v0.z *= msk; v0.w *= msk;
    v1.x *= msk; v1.y *= msk; v1.z *= msk; v1.w *= msk;
    float4* op = reinterpret_cast<float4*>(out + (size_t)gid * U_);
    op[0] = v0; op[1] = v1;
}

// ---------------------------------------------------------------------------
// 7. edge_concepts gather: out[bi, j, k, :] = rel[b, see[j], see[k], :]*m_j*m_k
// ---------------------------------------------------------------------------
__global__ void __launch_bounds__(256)
edge_gather_kernel(float* __restrict__ out) {
    int bi = blockIdx.x;
    int b  = bi >> 6;
    __shared__ int   ss[64];
    __shared__ float sm[64];
    int tid = threadIdx.x;
    if (tid < 64) {
        ss[tid] = g_see[bi*64 + tid];
        sm[tid] = (tid < g_cnt[bi]) ? 1.0f : 0.0f;
    }
    __syncthreads();
    float* outE = out + (size_t)NODE_OUT + (size_t)bi * (N_*N_*R_);
    const float* relb = g_rel + b * (N_*N_*R_);
    #pragma unroll
    for (int it = 0; it < 16; it++) {
        int idx = tid + 256*it;
        int j = idx >> 6, k = idx & 63;
        float m = sm[j] * sm[k];
        const float4* rp = reinterpret_cast<const float4*>(relb + (ss[j]*N_ + ss[k])*R_);
        float4 v0 = rp[0], v1 = rp[1];
        v0.x *= m; v0.y *= m; v0.z *= m; v0.w *= m;
        v1.x *= m; v1.y *= m; v1.z *= m; v1.w *= m;
        float4* op = reinterpret_cast<float4*>(outE + (size_t)idx * R_);
        op[0] = v0; op[1] = v1;
    }
}

// ---------------------------------------------------------------------------
extern "C" void kernel_launch(void* const* d_in, const int* in_sizes, int n_in,
                              void* d_out, int out_size) {
    const float* roi  = (const float*)d_in[0];
    const float* bbox = (const float*)d_in[1];
    const float* dir  = (const float*)d_in[2];
    const float* prio = (const float*)d_in[3];
    const float* w1   = (const float*)d_in[4];
    const float* b1   = (const float*)d_in[5];
    const float* g1   = (const float*)d_in[6];
    const float* bt1  = (const float*)d_in[7];
    const float* m1   = (const float*)d_in[8];
    const float* v1   = (const float*)d_in[9];
    const float* w2   = (const float*)d_in[10];
    const float* b2   = (const float*)d_in[11];
    const float* g2   = (const float*)d_in[12];
    const float* bt2  = (const float*)d_in[13];
    const float* m2   = (const float*)d_in[14];
    const float* v2   = (const float*)d_in[15];
    const float* w3   = (const float*)d_in[16];
    const float* b3   = (const float*)d_in[17];
    const float* wn   = (const float*)d_in[18];
    const float* bnc  = (const float*)d_in[19];
    const float* we1  = (const float*)d_in[20];
    const float* be1  = (const float*)d_in[21];
    const float* we2  = (const float*)d_in[22];
    const float* be2  = (const float*)d_in[23];
    const float* wei  = (const float*)d_in[24];
    const float* bei  = (const float*)d_in[25];
    const int*   eidx = (const int*)d_in[26];
    float* out = (float*)d_out;

    void *px1 = 0, *px2 = 0, *px3 = 0;
    cudaGetSymbolAddress(&px1, g_x1);
    cudaGetSymbolAddress(&px2, g_x2);
    cudaGetSymbolAddress(&px3, g_x3);

    build_see_kernel<<<B_, 64>>>(eidx);

    gemm_kernel<32,64,0><<<dim3(H1_/64, (B_*N_)/32), 128>>>(
        roi, w1, (float*)px1, B_*N_, H1_, C_, b1, g1, bt1, m1, v1);
    gemm_kernel<32,64,0><<<dim3(H2_/64, (B_*N_)/32), 128>>>(
        (const float*)px1, w2, (float*)px2, B_*N_, H2_, H1_, b2, g2, bt2, m2, v2);
    gemm_kernel<32,64,1><<<dim3(H3_/64, (B_*N_)/32), 128>>>(
        (const float*)px2, w3, (float*)px3, B_*N_, H3_, H2_, b3, 0, 0, 0, 0);

    node_head_kernel<<<(B_*N_*U_)/256, 256>>>(wn, bnc);
    edge_pq_kernel<<<(B_*N_*EH_)/256, 256>>>(bbox, dir, prio, we1, be1);
    edge_fused_kernel<<<B_*N_, 256>>>(we2, be2, wei, bei);

    node_gather_kernel<<<(B_*N_*N_)/256, 256>>>(out);
    edge_gather_kernel<<<B_*N_, 256>>>(out);
}

// round 4
// speedup vs baseline: 1.3206x; 1.3206x over previous
#include <cuda_runtime.h>
#include <math.h>

#define B_ 16
#define N_ 64
#define E_ 512
#define C_ 512
#define H1_ 256
#define H2_ 128
#define H3_ 64
#define U_ 8
#define R_ 8
#define EH_ 64
#define EPS_ 1e-5f
#define NODE_OUT (B_*N_*N_*U_)

typedef unsigned long long ull;

__device__ __align__(16) float g_nodec[B_*N_*U_];
__device__ __align__(16) float g_rel[B_*N_*N_*R_];
__device__ int g_see[B_*N_*N_];
__device__ int g_cnt[B_*N_];

__device__ __forceinline__ void fma2(ull& d, ull a, ull b) {
    asm("fma.rn.f32x2 %0, %1, %2, %0;" : "+l"(d) : "l"(a), "l"(b));
}
__device__ __forceinline__ ull dup2(float x) {
    ull r; asm("mov.b64 %0, {%1, %1};" : "=l"(r) : "f"(x)); return r;
}
__device__ __forceinline__ void unpack2(ull p, float& lo, float& hi) {
    asm("mov.b64 {%0, %1}, %2;" : "=f"(lo), "=f"(hi) : "l"(p));
}
__device__ __forceinline__ void cpa16(float* s, const float* g) {
    unsigned ss = (unsigned)__cvta_generic_to_shared(s);
    asm volatile("cp.async.cg.shared.global [%0], [%1], 16;" :: "r"(ss), "l"(g) : "memory");
}
__device__ __forceinline__ void cp_commit() {
    asm volatile("cp.async.commit_group;" ::: "memory");
}
template<int W> __device__ __forceinline__ void cp_wait() {
    asm volatile("cp.async.wait_group %0;" :: "n"(W) : "memory");
}
__device__ __forceinline__ float sigf(float x) { return 1.0f / (1.0f + __expf(-x)); }

// ---------------------------------------------------------------------------
// 1. see-table: one block per batch, thread n = dst node n (exact seq order).
// ---------------------------------------------------------------------------
__global__ void __launch_bounds__(64)
see_kernel(const int* __restrict__ ei) {
    __shared__ int sdst[E_], ssrc[E_];
    int b = blockIdx.x, n = threadIdx.x;
    const int* src = ei + b * 2 * E_;
    const int* dst = src + E_;
    for (int l = n; l < E_; l += 64) { ssrc[l] = src[l]; sdst[l] = dst[l]; }
    __syncthreads();
    int* row = g_see + (b * N_ + n) * N_;
    #pragma unroll 8
    for (int j = 0; j < N_; j++) row[j] = 0;
    row[0] = n;
    int c = 0;
    #pragma unroll 8
    for (int e = 0; e < E_; e++)
        if (sdst[e] == n) { c++; if (c < N_) row[c] = ssrc[e]; }
    g_cnt[b * N_ + n] = min(c + 1, N_);
}

// ---------------------------------------------------------------------------
// 2. Fused node MLP (L1+BN -> L2+BN -> L3 -> sigmoid head).
//    128 blocks x 128 thr, 8 rows/block, cp.async double-buffered weights.
// ---------------------------------------------------------------------------
__global__ void __launch_bounds__(128)
node_mlp_kernel(const float* __restrict__ roi,
    const float* __restrict__ w1, const float* __restrict__ b1,
    const float* __restrict__ g1, const float* __restrict__ bt1,
    const float* __restrict__ m1, const float* __restrict__ v1,
    const float* __restrict__ w2, const float* __restrict__ b2,
    const float* __restrict__ g2, const float* __restrict__ bt2,
    const float* __restrict__ m2, const float* __restrict__ v2,
    const float* __restrict__ w3, const float* __restrict__ b3,
    const float* __restrict__ wn, const float* __restrict__ bnc)
{
    extern __shared__ __align__(16) float sm[];
    float* sX  = sm;            // 8x512
    float* sX1 = sm + 4096;     // 8x256
    float* sX2 = sm + 6144;     // 8x128
    float* sX3 = sm + 7168;     // 8x64
    float* sWn = sm + 7680;     // 64x8
    float* sWa = sm + 8192;     // 8192
    float* sWb = sm + 16384;    // 8192
    int tid = threadIdx.x;
    int m0 = blockIdx.x * 8;

    {   // stage x rows + wn
        const float4* xs = (const float4*)(roi + (size_t)m0 * C_);
        float4* xd = (float4*)sX;
        #pragma unroll
        for (int q = 0; q < 8; q++) xd[tid + 128*q] = xs[tid + 128*q];
        cpa16(&sWn[tid*4], wn + tid*4);
    }
    #pragma unroll
    for (int j = 0; j < 16; j++) { int l = tid + 128*j; cpa16(&sWa[l*4], w1 + l*4); }
    cp_commit();
    __syncthreads();

    // ---- layer 1: 8x256, K=512 ----
    {
        int c = tid & 63, rp = tid >> 6;
        ull acc[4][2] = {};
        for (int ch = 0; ch < 16; ch++) {
            float* wb = (ch & 1) ? sWb : sWa;
            if (ch < 15) {
                const float* src = w1 + (ch+1) * 8192;
                float* dst = (ch & 1) ? sWa : sWb;
                #pragma unroll
                for (int j = 0; j < 16; j++) { int l = tid + 128*j; cpa16(&dst[l*4], src + l*4); }
            }
            cp_commit(); cp_wait<1>();
            __syncthreads();
            int k0 = ch * 32;
            #pragma unroll 8
            for (int k = 0; k < 32; k++) {
                ulonglong2 w = *(const ulonglong2*)&wb[k*256 + c*4];
                ull d0 = dup2(sX[(rp*4+0)*512 + k0 + k]);
                ull d1 = dup2(sX[(rp*4+1)*512 + k0 + k]);
                ull d2 = dup2(sX[(rp*4+2)*512 + k0 + k]);
                ull d3 = dup2(sX[(rp*4+3)*512 + k0 + k]);
                fma2(acc[0][0], d0, w.x); fma2(acc[0][1], d0, w.y);
                fma2(acc[1][0], d1, w.x); fma2(acc[1][1], d1, w.y);
                fma2(acc[2][0], d2, w.x); fma2(acc[2][1], d2, w.y);
                fma2(acc[3][0], d3, w.x); fma2(acc[3][1], d3, w.y);
            }
            __syncthreads();
        }
        float bb[4], sc[4], mm[4], be[4];
        #pragma unroll
        for (int j = 0; j < 4; j++) {
            int n = c*4 + j;
            bb[j] = b1[n]; sc[j] = g1[n] * rsqrtf(v1[n] + EPS_);
            mm[j] = m1[n]; be[j] = bt1[n];
        }
        #pragma unroll
        for (int rr = 0; rr < 4; rr++) {
            float v[4];
            unpack2(acc[rr][0], v[0], v[1]);
            unpack2(acc[rr][1], v[2], v[3]);
            float4 o;
            o.x = fmaxf((v[0] + bb[0] - mm[0]) * sc[0] + be[0], 0.0f);
            o.y = fmaxf((v[1] + bb[1] - mm[1]) * sc[1] + be[1], 0.0f);
            o.z = fmaxf((v[2] + bb[2] - mm[2]) * sc[2] + be[2], 0.0f);
            o.w = fmaxf((v[3] + bb[3] - mm[3]) * sc[3] + be[3], 0.0f);
            *(float4*)&sX1[(rp*4+rr)*256 + c*4] = o;
        }
    }
    __syncthreads();

    // ---- layer 2: 8x128, K=256 ----
    {
        #pragma unroll
        for (int j = 0; j < 8; j++) { int l = tid + 128*j; cpa16(&sWa[l*4], w2 + l*4); }
        cp_commit();
        int c = tid & 31, rp = tid >> 5;
        ull acc[4][2] = {};
        for (int ch = 0; ch < 8; ch++) {
            float* wb = (ch & 1) ? sWb : sWa;
            if (ch < 7) {
                const float* src = w2 + (ch+1) * 4096;
                float* dst = (ch & 1) ? sWa : sWb;
                #pragma unroll
                for (int j = 0; j < 8; j++) { int l = tid + 128*j; cpa16(&dst[l*4], src + l*4); }
            }
            cp_commit(); cp_wait<1>();
            __syncthreads();
            if (tid < 64) {
                int k0 = ch * 32;
                #pragma unroll 8
                for (int k = 0; k < 32; k++) {
                    ulonglong2 w = *(const ulonglong2*)&wb[k*128 + c*4];
                    ull d0 = dup2(sX1[(rp*4+0)*256 + k0 + k]);
                    ull d1 = dup2(sX1[(rp*4+1)*256 + k0 + k]);
                    ull d2 = dup2(sX1[(rp*4+2)*256 + k0 + k]);
                    ull d3 = dup2(sX1[(rp*4+3)*256 + k0 + k]);
                    fma2(acc[0][0], d0, w.x); fma2(acc[0][1], d0, w.y);
                    fma2(acc[1][0], d1, w.x); fma2(acc[1][1], d1, w.y);
                    fma2(acc[2][0], d2, w.x); fma2(acc[2][1], d2, w.y);
                    fma2(acc[3][0], d3, w.x); fma2(acc[3][1], d3, w.y);
                }
            }
            __syncthreads();
        }
        if (tid < 64) {
            float bb[4], sc[4], mm[4], be[4];
            #pragma unroll
            for (int j = 0; j < 4; j++) {
                int n = c*4 + j;
                bb[j] = b2[n]; sc[j] = g2[n] * rsqrtf(v2[n] + EPS_);
                mm[j] = m2[n]; be[j] = bt2[n];
            }
            #pragma unroll
            for (int rr = 0; rr < 4; rr++) {
                float v[4];
                unpack2(acc[rr][0], v[0], v[1]);
                unpack2(acc[rr][1], v[2], v[3]);
                float4 o;
                o.x = fmaxf((v[0] + bb[0] - mm[0]) * sc[0] + be[0], 0.0f);
                o.y = fmaxf((v[1] + bb[1] - mm[1]) * sc[1] + be[1], 0.0f);
                o.z = fmaxf((v[2] + bb[2] - mm[2]) * sc[2] + be[2], 0.0f);
                o.w = fmaxf((v[3] + bb[3] - mm[3]) * sc[3] + be[3], 0.0f);
                *(float4*)&sX2[(rp*4+rr)*128 + c*4] = o;
            }
        }
    }
    __syncthreads();

    // ---- layer 3: 8x64, K=128 (whole w3 in smem) ----
    #pragma unroll
    for (int j = 0; j < 16; j++) { int l = tid + 128*j; cpa16(&sWa[l*4], w3 + l*4); }
    cp_commit(); cp_wait<0>();
    __syncthreads();
    if (tid < 32) {
        int c = tid & 15, rp = tid >> 4;
        ull acc[4][2] = {};
        #pragma unroll 8
        for (int k = 0; k < 128; k++) {
            ulonglong2 w = *(const ulonglong2*)&sWa[k*64 + c*4];
            ull d0 = dup2(sX2[(rp*4+0)*128 + k]);
            ull d1 = dup2(sX2[(rp*4+1)*128 + k]);
            ull d2 = dup2(sX2[(rp*4+2)*128 + k]);
            ull d3 = dup2(sX2[(rp*4+3)*128 + k]);
            fma2(acc[0][0], d0, w.x); fma2(acc[0][1], d0, w.y);
            fma2(acc[1][0], d1, w.x); fma2(acc[1][1], d1, w.y);
            fma2(acc[2][0], d2, w.x); fma2(acc[2][1], d2, w.y);
            fma2(acc[3][0], d3, w.x); fma2(acc[3][1], d3, w.y);
        }
        #pragma unroll
        for (int rr = 0; rr < 4; rr++) {
            float v[4];
            unpack2(acc[rr][0], v[0], v[1]);
            unpack2(acc[rr][1], v[2], v[3]);
            float4 o;
            o.x = fmaxf(v[0] + b3[c*4+0], 0.0f);
            o.y = fmaxf(v[1] + b3[c*4+1], 0.0f);
            o.z = fmaxf(v[2] + b3[c*4+2], 0.0f);
            o.w = fmaxf(v[3] + b3[c*4+3], 0.0f);
            *(float4*)&sX3[(rp*4+rr)*64 + c*4] = o;
        }
    }
    __syncthreads();

    // ---- head ----
    if (tid < 64) {
        int r = tid >> 3, u = tid & 7;
        float s = bnc[u];
        #pragma unroll 8
        for (int k = 0; k < H3_; k++) s = fmaf(sX3[r*64 + k], sWn[k*8 + u], s);
        g_nodec[(m0 + r)*U_ + u] = sigf(s);
    }
}

// ---------------------------------------------------------------------------
// 3. Fused edge MLP per (b,i): attr -> factorized layer-1 -> e2 -> rel.
// ---------------------------------------------------------------------------
__global__ void __launch_bounds__(256)
edge_kernel(const float* __restrict__ bbox, const float* __restrict__ dir,
            const float* __restrict__ prio,
            const float* __restrict__ we1, const float* __restrict__ be1,
            const float* __restrict__ we2, const float* __restrict__ be2,
            const float* __restrict__ wei, const float* __restrict__ bei)
{
    __shared__ __align__(16) float sE[64*68];
    __shared__ __align__(16) float sW2[64*64];
    __shared__ __align__(16) float sWei[64*8];
    __shared__ float sAttr[64*9], sWe1[18*64], sP[64], sBe2[64], sBei[8];
    int tid = threadIdx.x, bi = blockIdx.x;
    int b = bi >> 6, i = bi & 63;

    for (int l = tid; l < 576; l += 256) {
        int r = l / 9, c = l - r*9;
        float v;
        if (c < 4)      v = bbox[(b*N_ + r)*4 + c] * (1.0f/1024.0f);
        else if (c < 8) v = dir[(b*N_ + r)*4 + c - 4];
        else            v = prio[b*N_ + r];
        sAttr[l] = v;
    }
    for (int l = tid; l < 1152; l += 256) sWe1[l] = we1[l];
    for (int l = tid; l < 1024; l += 256) ((float4*)sW2)[l] = ((const float4*)we2)[l];
    for (int l = tid; l < 512; l += 256) sWei[l] = wei[l];
    if (tid < 64) sBe2[tid] = be2[tid];
    if (tid < 8)  sBei[tid] = bei[tid];
    __syncthreads();

    if (tid < 64) {
        float p = be1[tid];
        #pragma unroll
        for (int c = 0; c < 9; c++) p = fmaf(sAttr[i*9 + c], sWe1[c*64 + tid], p);
        sP[tid] = p;
    }
    __syncthreads();

    {   // e1[j][h] = relu(P[h] + attr_j @ we1[9:])
        int j = tid >> 2, hq = tid & 3;
        float a[9];
        #pragma unroll
        for (int c = 0; c < 9; c++) a[c] = sAttr[j*9 + c];
        #pragma unroll
        for (int h0 = hq*16; h0 < hq*16 + 16; h0 += 4) {
            float4 o; float* op = &o.x;
            #pragma unroll
            for (int t = 0; t < 4; t++) {
                int h = h0 + t;
                float q = 0.0f;
                #pragma unroll
                for (int c = 0; c < 9; c++) q = fmaf(a[c], sWe1[(9+c)*64 + h], q);
                op[t] = fmaxf(sP[h] + q, 0.0f);
            }
            *(float4*)&sE[j*68 + h0] = o;
        }
    }
    __syncthreads();

    // e2 = relu(e1 @ we2 + be2): 64x64 K=64 f32x2
    int tc = tid & 15, tr = tid >> 4;
    {
        ull acc[4][2] = {};
        #pragma unroll 16
        for (int h = 0; h < 64; h++) {
            ulonglong2 w = *(const ulonglong2*)&sW2[h*64 + tc*4];
            ull d0 = dup2(sE[(tr*4+0)*68 + h]);
            ull d1 = dup2(sE[(tr*4+1)*68 + h]);
            ull d2 = dup2(sE[(tr*4+2)*68 + h]);
            ull d3 = dup2(sE[(tr*4+3)*68 + h]);
            fma2(acc[0][0], d0, w.x); fma2(acc[0][1], d0, w.y);
            fma2(acc[1][0], d1, w.x); fma2(acc[1][1], d1, w.y);
            fma2(acc[2][0], d2, w.x); fma2(acc[2][1], d2, w.y);
            fma2(acc[3][0], d3, w.x); fma2(acc[3][1], d3, w.y);
        }
        __syncthreads();
        #pragma unroll
        for (int rr = 0; rr < 4; rr++) {
            float v[4];
            unpack2(acc[rr][0], v[0], v[1]);
            unpack2(acc[rr][1], v[2], v[3]);
            float4 o;
            o.x = fmaxf(v[0] + sBe2[tc*4+0], 0.0f);
            o.y = fmaxf(v[1] + sBe2[tc*4+1], 0.0f);
            o.z = fmaxf(v[2] + sBe2[tc*4+2], 0.0f);
            o.w = fmaxf(v[3] + sBe2[tc*4+3], 0.0f);
            *(float4*)&sE[(tr*4+rr)*68 + tc*4] = o;
        }
    }
    __syncthreads();

    if (tid < 128) {  // rel = sigmoid(e2 @ wei + bei)
        int j = tid >> 1, rh = tid & 1;
        float a0 = sBei[rh*4+0], a1 = sBei[rh*4+1], a2 = sBei[rh*4+2], a3 = sBei[rh*4+3];
        #pragma unroll 16
        for (int o = 0; o < 64; o++) {
            float e = sE[j*68 + o];
            float4 w = *(const float4*)&sWei[o*8 + rh*4];
            a0 = fmaf(e, w.x, a0); a1 = fmaf(e, w.y, a1);
            a2 = fmaf(e, w.z, a2); a3 = fmaf(e, w.w, a3);
        }
        float4 o;
        o.x = sigf(a0); o.y = sigf(a1); o.z = sigf(a2); o.w = sigf(a3);
        *(float4*)&g_rel[(bi*64 + j)*8 + rh*4] = o;
    }
}

// ---------------------------------------------------------------------------
// 4. Fused gathers: block bg caches rel[b] (128KB smem) + node_c[b], emits
//    8 output rows with streaming stores.
// ---------------------------------------------------------------------------
__global__ void __launch_bounds__(256)
gather_kernel(float* __restrict__ out) {
    extern __shared__ __align__(16) float gsm[];
    float* sRel  = gsm;                 // 32768
    float* sNode = gsm + 32768;         // 512
    int*   sS    = (int*)(gsm + 33280); // 512
    float* sM    = gsm + 33792;         // 512
    int tid = threadIdx.x, bg = blockIdx.x;
    int b = bg >> 3, i0 = (bg & 7) * 8;

    const float4* relb = (const float4*)(g_rel + b * (N_*N_*R_));
    #pragma unroll
    for (int q = 0; q < 32; q++) ((float4*)sRel)[tid + 256*q] = relb[tid + 256*q];
    if (tid < 128) ((float4*)sNode)[tid] = ((const float4*)(g_nodec + b*N_*U_))[tid];
    for (int l = tid; l < 512; l += 256) {
        int u = l >> 6, j = l & 63;
        int row = b*N_ + i0 + u;
        sS[l] = g_see[row*N_ + j];
        sM[l] = (j < g_cnt[row]) ? 1.0f : 0.0f;
    }
    __syncthreads();

    #pragma unroll
    for (int u = 0; u < 8; u++) {
        int bi = bg*8 + u;
        if (tid < 128) {
            int j = tid >> 1, h = tid & 1;
            float m = sM[u*64 + j];
            float4 v = *(const float4*)&sNode[sS[u*64 + j]*8 + h*4];
            v.x *= m; v.y *= m; v.z *= m; v.w *= m;
            __stcs((float4*)(out + (size_t)bi * 512) + tid, v);
        }
        float* oE = out + (size_t)NODE_OUT + (size_t)bi * (N_*N_*R_);
        #pragma unroll
        for (int it = 0; it < 16; it++) {
            int idx = it*256 + tid;
            int j = idx >> 6, k = idx & 63;
            float m = sM[u*64 + j] * sM[u*64 + k];
            const float4* rp = (const float4*)&sRel[(sS[u*64 + j]*64 + sS[u*64 + k]) * 8];
            float4 v0 = rp[0], v1 = rp[1];
            v0.x *= m; v0.y *= m; v0.z *= m; v0.w *= m;
            v1.x *= m; v1.y *= m; v1.z *= m; v1.w *= m;
            __stcs((float4*)oE + idx*2,     v0);
            __stcs((float4*)oE + idx*2 + 1, v1);
        }
    }
}

// ---------------------------------------------------------------------------
extern "C" void kernel_launch(void* const* d_in, const int* in_sizes, int n_in,
                              void* d_out, int out_size) {
    const float* roi  = (const float*)d_in[0];
    const float* bbox = (const float*)d_in[1];
    const float* dir  = (const float*)d_in[2];
    const float* prio = (const float*)d_in[3];
    const float* w1   = (const float*)d_in[4];
    const float* b1   = (const float*)d_in[5];
    const float* g1   = (const float*)d_in[6];
    const float* bt1  = (const float*)d_in[7];
    const float* m1   = (const float*)d_in[8];
    const float* v1   = (const float*)d_in[9];
    const float* w2   = (const float*)d_in[10];
    const float* b2   = (const float*)d_in[11];
    const float* g2   = (const float*)d_in[12];
    const float* bt2  = (const float*)d_in[13];
    const float* m2   = (const float*)d_in[14];
    const float* v2   = (const float*)d_in[15];
    const float* w3   = (const float*)d_in[16];
    const float* b3   = (const float*)d_in[17];
    const float* wn   = (const float*)d_in[18];
    const float* bnc  = (const float*)d_in[19];
    const float* we1  = (const float*)d_in[20];
    const float* be1  = (const float*)d_in[21];
    const float* we2  = (const float*)d_in[22];
    const float* be2  = (const float*)d_in[23];
    const float* wei  = (const float*)d_in[24];
    const float* bei  = (const float*)d_in[25];
    const int*   eidx = (const int*)d_in[26];
    float* out = (float*)d_out;

    cudaFuncSetAttribute(node_mlp_kernel,
        cudaFuncAttributeMaxDynamicSharedMemorySize, 24576 * 4);
    cudaFuncSetAttribute(gather_kernel,
        cudaFuncAttributeMaxDynamicSharedMemorySize, 34304 * 4);

    see_kernel<<<B_, 64>>>(eidx);
    node_mlp_kernel<<<128, 128, 24576 * 4>>>(roi,
        w1, b1, g1, bt1, m1, v1,
        w2, b2, g2, bt2, m2, v2,
        w3, b3, wn, bnc);
    edge_kernel<<<B_*N_, 256>>>(bbox, dir, prio, we1, be1, we2, be2, wei, bei);
    gather_kernel<<<128, 256, 34304 * 4>>>(out);
}

// round 6
// speedup vs baseline: 1.5663x; 1.1860x over previous
#include <cuda_runtime.h>
#include <math.h>

#define B_ 16
#define N_ 64
#define E_ 512
#define C_ 512
#define H1_ 256
#define H2_ 128
#define H3_ 64
#define U_ 8
#define R_ 8
#define EH_ 64
#define EPS_ 1e-5f
#define NODE_OUT (B_*N_*N_*U_)

typedef unsigned long long ull;

__device__ __align__(16) float g_nodec[B_*N_*U_];
__device__ __align__(16) float g_rel[B_*N_*N_*R_];
__device__ int g_see[B_*N_*N_];
__device__ int g_cnt[B_*N_];

__device__ __forceinline__ void fma2(ull& d, ull a, ull b) {
    asm("fma.rn.f32x2 %0, %1, %2, %0;" : "+l"(d) : "l"(a), "l"(b));
}
__device__ __forceinline__ ull dup2(float x) {
    ull r; asm("mov.b64 %0, {%1, %1};" : "=l"(r) : "f"(x)); return r;
}
__device__ __forceinline__ void unpack2(ull p, float& lo, float& hi) {
    asm("mov.b64 {%0, %1}, %2;" : "=f"(lo), "=f"(hi) : "l"(p));
}
__device__ __forceinline__ void cpa16(float* s, const float* g) {
    unsigned ss = (unsigned)__cvta_generic_to_shared(s);
    asm volatile("cp.async.cg.shared.global [%0], [%1], 16;" :: "r"(ss), "l"(g) : "memory");
}
__device__ __forceinline__ void cp_commit() {
    asm volatile("cp.async.commit_group;" ::: "memory");
}
template<int W> __device__ __forceinline__ void cp_wait() {
    asm volatile("cp.async.wait_group %0;" :: "n"(W) : "memory");
}
__device__ __forceinline__ float sigf(float x) { return 1.0f / (1.0f + __expf(-x)); }

// ===========================================================================
// Role 1: edge MLP per (b,i): factorized layer-1 -> e2 -> rel
// ===========================================================================
__device__ void edge_role(float* sm, int bi,
    const float* __restrict__ bbox, const float* __restrict__ dir,
    const float* __restrict__ prio,
    const float* __restrict__ we1, const float* __restrict__ be1,
    const float* __restrict__ we2, const float* __restrict__ be2,
    const float* __restrict__ wei, const float* __restrict__ bei)
{
    float* sE    = sm;           // 4352 (64x68)
    float* sW2   = sm + 4352;    // 4096
    float* sWei  = sm + 8448;    // 512
    float* sWe1  = sm + 8960;    // 1152
    float* sAttr = sm + 10112;   // 576
    float* sP    = sm + 10688;   // 64
    float* sBe2  = sm + 10752;   // 64
    float* sBei  = sm + 10816;   // 8
    int tid = threadIdx.x;
    int b = bi >> 6, i = bi & 63;

    for (int l = tid; l < 576; l += 256) {
        int r = l / 9, c = l - r*9;
        float v;
        if (c < 4)      v = bbox[(b*N_ + r)*4 + c] * (1.0f/1024.0f);
        else if (c < 8) v = dir[(b*N_ + r)*4 + c - 4];
        else            v = prio[b*N_ + r];
        sAttr[l] = v;
    }
    for (int l = tid; l < 1152; l += 256) sWe1[l] = we1[l];
    for (int l = tid; l < 1024; l += 256) ((float4*)sW2)[l] = ((const float4*)we2)[l];
    for (int l = tid; l < 512; l += 256) sWei[l] = wei[l];
    if (tid < 64) sBe2[tid] = be2[tid];
    if (tid < 8)  sBei[tid] = bei[tid];
    __syncthreads();

    if (tid < 64) {
        float p = be1[tid];
        #pragma unroll
        for (int c = 0; c < 9; c++) p = fmaf(sAttr[i*9 + c], sWe1[c*64 + tid], p);
        sP[tid] = p;
    }
    __syncthreads();

    {   // e1[j][h] = relu(P[h] + attr_j @ we1[9:])
        int j = tid >> 2, hq = tid & 3;
        float a[9];
        #pragma unroll
        for (int c = 0; c < 9; c++) a[c] = sAttr[j*9 + c];
        #pragma unroll
        for (int h0 = hq*16; h0 < hq*16 + 16; h0 += 4) {
            float4 o; float* op = &o.x;
            #pragma unroll
            for (int t = 0; t < 4; t++) {
                int h = h0 + t;
                float q = 0.0f;
                #pragma unroll
                for (int c = 0; c < 9; c++) q = fmaf(a[c], sWe1[(9+c)*64 + h], q);
                op[t] = fmaxf(sP[h] + q, 0.0f);
            }
            *(float4*)&sE[j*68 + h0] = o;
        }
    }
    __syncthreads();

    // e2 = relu(e1 @ we2 + be2): 64x64 K=64 f32x2
    int tc = tid & 15, tr = tid >> 4;
    {
        ull acc[4][2] = {};
        #pragma unroll 16
        for (int h = 0; h < 64; h++) {
            ulonglong2 w = *(const ulonglong2*)&sW2[h*64 + tc*4];
            ull d0 = dup2(sE[(tr*4+0)*68 + h]);
            ull d1 = dup2(sE[(tr*4+1)*68 + h]);
            ull d2 = dup2(sE[(tr*4+2)*68 + h]);
            ull d3 = dup2(sE[(tr*4+3)*68 + h]);
            fma2(acc[0][0], d0, w.x); fma2(acc[0][1], d0, w.y);
            fma2(acc[1][0], d1, w.x); fma2(acc[1][1], d1, w.y);
            fma2(acc[2][0], d2, w.x); fma2(acc[2][1], d2, w.y);
            fma2(acc[3][0], d3, w.x); fma2(acc[3][1], d3, w.y);
        }
        __syncthreads();
        #pragma unroll
        for (int rr = 0; rr < 4; rr++) {
            float v[4];
            unpack2(acc[rr][0], v[0], v[1]);
            unpack2(acc[rr][1], v[2], v[3]);
            float4 o;
            o.x = fmaxf(v[0] + sBe2[tc*4+0], 0.0f);
            o.y = fmaxf(v[1] + sBe2[tc*4+1], 0.0f);
            o.z = fmaxf(v[2] + sBe2[tc*4+2], 0.0f);
            o.w = fmaxf(v[3] + sBe2[tc*4+3], 0.0f);
            *(float4*)&sE[(tr*4+rr)*68 + tc*4] = o;
        }
    }
    __syncthreads();

    if (tid < 128) {  // rel = sigmoid(e2 @ wei + bei)
        int j = tid >> 1, rh = tid & 1;
        float a0 = sBei[rh*4+0], a1 = sBei[rh*4+1], a2 = sBei[rh*4+2], a3 = sBei[rh*4+3];
        #pragma unroll 16
        for (int o = 0; o < 64; o++) {
            float e = sE[j*68 + o];
            float4 w = *(const float4*)&sWei[o*8 + rh*4];
            a0 = fmaf(e, w.x, a0); a1 = fmaf(e, w.y, a1);
            a2 = fmaf(e, w.z, a2); a3 = fmaf(e, w.w, a3);
        }
        float4 o;
        o.x = sigf(a0); o.y = sigf(a1); o.z = sigf(a2); o.w = sigf(a3);
        *(float4*)&g_rel[(bi*64 + j)*8 + rh*4] = o;
    }
}

// ===========================================================================
// Role 2: node MLP (256 threads, 8 rows per block)
// ===========================================================================
__device__ void node_role(float* sm, int blk, const float* __restrict__ roi,
    const float* __restrict__ w1, const float* __restrict__ b1,
    const float* __restrict__ g1, const float* __restrict__ bt1,
    const float* __restrict__ m1, const float* __restrict__ v1,
    const float* __restrict__ w2, const float* __restrict__ b2,
    const float* __restrict__ g2, const float* __restrict__ bt2,
    const float* __restrict__ m2, const float* __restrict__ v2,
    const float* __restrict__ w3, const float* __restrict__ b3,
    const float* __restrict__ wn, const float* __restrict__ bnc)
{
    float* sX  = sm;            // 4096
    float* sX1 = sm + 4096;     // 2048
    float* sX2 = sm + 6144;     // 1024
    float* sX3 = sm + 7168;     // 512
    float* sWn = sm + 7680;     // 512
    float* sWa = sm + 8192;     // 8192
    float* sWb = sm + 16384;    // 8192
    int tid = threadIdx.x;
    int m0 = blk * 8;

    {
        const float4* xs = (const float4*)(roi + (size_t)m0 * C_);
        float4* xd = (float4*)sX;
        #pragma unroll
        for (int q = 0; q < 4; q++) xd[tid + 256*q] = xs[tid + 256*q];
        if (tid < 128) cpa16(&sWn[tid*4], wn + tid*4);
    }
    #pragma unroll
    for (int j = 0; j < 8; j++) { int l = tid + 256*j; cpa16(&sWa[l*4], w1 + l*4); }
    cp_commit();
    __syncthreads();

    // ---- layer 1: 8x256, K=512; thread -> 2 rows x 4 cols ----
    {
        int c = tid & 63, rp = tid >> 6;
        ull acc[2][2] = {};
        for (int ch = 0; ch < 16; ch++) {
            float* wb = (ch & 1) ? sWb : sWa;
            if (ch < 15) {
                const float* src = w1 + (ch+1) * 8192;
                float* dst = (ch & 1) ? sWa : sWb;
                #pragma unroll
                for (int j = 0; j < 8; j++) { int l = tid + 256*j; cpa16(&dst[l*4], src + l*4); }
            }
            cp_commit(); cp_wait<1>();
            __syncthreads();
            int k0 = ch * 32;
            #pragma unroll 8
            for (int k = 0; k < 32; k++) {
                ulonglong2 w = *(const ulonglong2*)&wb[k*256 + c*4];
                ull d0 = dup2(sX[(rp*2+0)*512 + k0 + k]);
                ull d1 = dup2(sX[(rp*2+1)*512 + k0 + k]);
                fma2(acc[0][0], d0, w.x); fma2(acc[0][1], d0, w.y);
                fma2(acc[1][0], d1, w.x); fma2(acc[1][1], d1, w.y);
            }
            __syncthreads();
        }
        float bb[4], sc[4], mm[4], be[4];
        #pragma unroll
        for (int j = 0; j < 4; j++) {
            int n = c*4 + j;
            bb[j] = b1[n]; sc[j] = g1[n] * rsqrtf(v1[n] + EPS_);
            mm[j] = m1[n]; be[j] = bt1[n];
        }
        #pragma unroll
        for (int rr = 0; rr < 2; rr++) {
            float v[4];
            unpack2(acc[rr][0], v[0], v[1]);
            unpack2(acc[rr][1], v[2], v[3]);
            float4 o;
            o.x = fmaxf((v[0] + bb[0] - mm[0]) * sc[0] + be[0], 0.0f);
            o.y = fmaxf((v[1] + bb[1] - mm[1]) * sc[1] + be[1], 0.0f);
            o.z = fmaxf((v[2] + bb[2] - mm[2]) * sc[2] + be[2], 0.0f);
            o.w = fmaxf((v[3] + bb[3] - mm[3]) * sc[3] + be[3], 0.0f);
            *(float4*)&sX1[(rp*2+rr)*256 + c*4] = o;
        }
    }
    __syncthreads();

    // ---- layer 2: 8x128, K=256; thread -> 1 row x 4 cols ----
    {
        #pragma unroll
        for (int j = 0; j < 4; j++) { int l = tid + 256*j; cpa16(&sWa[l*4], w2 + l*4); }
        cp_commit();
        int c = tid & 31, rp = tid >> 5;
        ull acc[2] = {};
        for (int ch = 0; ch < 8; ch++) {
            float* wb = (ch & 1) ? sWb : sWa;
            if (ch < 7) {
                const float* src = w2 + (ch+1) * 4096;
                float* dst = (ch & 1) ? sWa : sWb;
                #pragma unroll
                for (int j = 0; j < 4; j++) { int l = tid + 256*j; cpa16(&dst[l*4], src + l*4); }
            }
            cp_commit(); cp_wait<1>();
            __syncthreads();
            int k0 = ch * 32;
            #pragma unroll 8
            for (int k = 0; k < 32; k++) {
                ulonglong2 w = *(const ulonglong2*)&wb[k*128 + c*4];
                ull d0 = dup2(sX1[rp*256 + k0 + k]);
                fma2(acc[0], d0, w.x); fma2(acc[1], d0, w.y);
            }
            __syncthreads();
        }
        float v[4];
        unpack2(acc[0], v[0], v[1]);
        unpack2(acc[1], v[2], v[3]);
        float4 o; float* op = &o.x;
        #pragma unroll
        for (int j = 0; j < 4; j++) {
            int n = c*4 + j;
            float scv = g2[n] * rsqrtf(v2[n] + EPS_);
            op[j] = fmaxf((v[j] + b2[n] - m2[n]) * scv + bt2[n], 0.0f);
        }
        *(float4*)&sX2[rp*128 + c*4] = o;
    }
    __syncthreads();

    // ---- layer 3: 8x64, K=128 (whole w3 staged) ----
    #pragma unroll
    for (int j = 0; j < 8; j++) { int l = tid + 256*j; cpa16(&sWa[l*4], w3 + l*4); }
    cp_commit(); cp_wait<0>();
    __syncthreads();
    if (tid < 128) {
        int c = tid & 15, rp = tid >> 4;
        ull acc[2] = {};
        #pragma unroll 8
        for (int k = 0; k < 128; k++) {
            ulonglong2 w = *(const ulonglong2*)&sWa[k*64 + c*4];
            ull d0 = dup2(sX2[rp*128 + k]);
            fma2(acc[0], d0, w.x); fma2(acc[1], d0, w.y);
        }
        float v[4];
        unpack2(acc[0], v[0], v[1]);
        unpack2(acc[1], v[2], v[3]);
        float4 o;
        o.x = fmaxf(v[0] + b3[c*4+0], 0.0f);
        o.y = fmaxf(v[1] + b3[c*4+1], 0.0f);
        o.z = fmaxf(v[2] + b3[c*4+2], 0.0f);
        o.w = fmaxf(v[3] + b3[c*4+3], 0.0f);
        *(float4*)&sX3[rp*64 + c*4] = o;
    }
    __syncthreads();

    if (tid < 64) {
        int r = tid >> 3, u = tid & 7;
        float s = bnc[u];
        #pragma unroll 8
        for (int k = 0; k < H3_; k++) s = fmaf(sX3[r*64 + k], sWn[k*8 + u], s);
        g_nodec[(m0 + r)*U_ + u] = sigf(s);
    }
}

// ===========================================================================
// Role 3: see-table build (segmented count + prefix, exact sequential order)
// ===========================================================================
__device__ void see_role(int* ism, int b, const int* __restrict__ ei) {
    int* ssrc = ism;          // 512
    int* sdst = ism + 512;    // 512
    int* scnt = ism + 1024;   // 256
    int tid = threadIdx.x;
    for (int l = tid; l < E_; l += 256) {
        ssrc[l] = ei[b*2*E_ + l];
        sdst[l] = ei[b*2*E_ + E_ + l];
    }
    __syncthreads();
    int s = tid >> 6;          // segment 0..3 (128 edges each)
    int n = tid & 63;
    int* row = g_see + (b*N_ + n) * N_;
    #pragma unroll
    for (int q = 0; q < 16; q++) row[s*16 + q] = 0;
    int c = 0;
    #pragma unroll 8
    for (int e = s*128; e < s*128 + 128; e++) if (sdst[e] == n) c++;
    scnt[tid] = c;
    __syncthreads();           // zeroing + counts visible
    int base = 0;
    #pragma unroll
    for (int t = 0; t < 4; t++) if (t < s) base += scnt[t*64 + n];
    int p = base + 1;
    #pragma unroll 8
    for (int e = s*128; e < s*128 + 128; e++) {
        if (sdst[e] == n) { if (p < N_) row[p] = ssrc[e]; p++; }
    }
    if (s == 0) row[0] = n;
    if (s == 3) g_cnt[b*N_ + n] = min(base + c + 1, N_);
}

// ===========================================================================
// Mega kernel: blocks [0,1024) edge, [1024,1152) node, [1152,1168) see
// ===========================================================================
__global__ void __launch_bounds__(256)
mega_kernel(const float* __restrict__ roi,
    const float* __restrict__ bbox, const float* __restrict__ dir,
    const float* __restrict__ prio,
    const float* __restrict__ w1, const float* __restrict__ b1,
    const float* __restrict__ g1, const float* __restrict__ bt1,
    const float* __restrict__ m1, const float* __restrict__ v1,
    const float* __restrict__ w2, const float* __restrict__ b2,
    const float* __restrict__ g2, const float* __restrict__ bt2,
    const float* __restrict__ m2, const float* __restrict__ v2,
    const float* __restrict__ w3, const float* __restrict__ b3,
    const float* __restrict__ wn, const float* __restrict__ bnc,
    const float* __restrict__ we1, const float* __restrict__ be1,
    const float* __restrict__ we2, const float* __restrict__ be2,
    const float* __restrict__ wei, const float* __restrict__ bei,
    const int* __restrict__ eidx)
{
    extern __shared__ __align__(16) float smx[];
    int blk = blockIdx.x;
    if (blk < 1024) {
        edge_role(smx, blk, bbox, dir, prio, we1, be1, we2, be2, wei, bei);
    } else if (blk < 1152) {
        node_role(smx, blk - 1024, roi, w1, b1, g1, bt1, m1, v1,
                  w2, b2, g2, bt2, m2, v2, w3, b3, wn, bnc);
    } else {
        see_role((int*)smx, blk - 1152, eidx);
    }
}

// ===========================================================================
// Gather: one block per output row bi; rel read straight from L2.
// ===========================================================================
__global__ void __launch_bounds__(256)
gather_kernel(float* __restrict__ out) {
    __shared__ int   ss[64];
    __shared__ float sm[64];
    int tid = threadIdx.x, bi = blockIdx.x;
    int b = bi >> 6;
    if (tid < 64) {
        ss[tid] = g_see[bi*64 + tid];
        sm[tid] = (tid < g_cnt[bi]) ? 1.0f : 0.0f;
    }
    __syncthreads();

    if (tid < 128) {   // node_concepts row bi
        int j = tid >> 1, h = tid & 1;
        float m = sm[j];
        float4 v = __ldg((const float4*)(g_nodec + (b*N_ + ss[j])*U_) + h);
        v.x *= m; v.y *= m; v.z *= m; v.w *= m;
        __stcs((float4*)(out + (size_t)bi * 512) + tid, v);
    }

    const float4* relb = (const float4*)(g_rel + b * (N_*N_*R_));
    float* oE = out + (size_t)NODE_OUT + (size_t)bi * (N_*N_*R_);
    #pragma unroll
    for (int it = 0; it < 16; it++) {
        int idx = it*256 + tid;
        int j = idx >> 6, k = idx & 63;
        float m = sm[j] * sm[k];
        const float4* rp = relb + (ss[j]*64 + ss[k]) * 2;
        float4 v0 = __ldg(rp), v1 = __ldg(rp + 1);
        v0.x *= m; v0.y *= m; v0.z *= m; v0.w *= m;
        v1.x *= m; v1.y *= m; v1.z *= m; v1.w *= m;
        __stcs((float4*)oE + idx*2,     v0);
        __stcs((float4*)oE + idx*2 + 1, v1);
    }
}

// ===========================================================================
extern "C" void kernel_launch(void* const* d_in, const int* in_sizes, int n_in,
                              void* d_out, int out_size) {
    const float* roi  = (const float*)d_in[0];
    const float* bbox = (const float*)d_in[1];
    const float* dir  = (const float*)d_in[2];
    const float* prio = (const float*)d_in[3];
    const float* w1   = (const float*)d_in[4];
    const float* b1   = (const float*)d_in[5];
    const float* g1   = (const float*)d_in[6];
    const float* bt1  = (const float*)d_in[7];
    const float* m1   = (const float*)d_in[8];
    const float* v1   = (const float*)d_in[9];
    const float* w2   = (const float*)d_in[10];
    const float* b2   = (const float*)d_in[11];
    const float* g2   = (const float*)d_in[12];
    const float* bt2  = (const float*)d_in[13];
    const float* m2   = (const float*)d_in[14];
    const float* v2   = (const float*)d_in[15];
    const float* w3   = (const float*)d_in[16];
    const float* b3   = (const float*)d_in[17];
    const float* wn   = (const float*)d_in[18];
    const float* bnc  = (const float*)d_in[19];
    const float* we1  = (const float*)d_in[20];
    const float* be1  = (const float*)d_in[21];
    const float* we2  = (const float*)d_in[22];
    const float* be2  = (const float*)d_in[23];
    const float* wei  = (const float*)d_in[24];
    const float* bei  = (const float*)d_in[25];
    const int*   eidx = (const int*)d_in[26];
    float* out = (float*)d_out;

    cudaFuncSetAttribute(mega_kernel,
        cudaFuncAttributeMaxDynamicSharedMemorySize, 98304);

    mega_kernel<<<1168, 256, 98304>>>(roi, bbox, dir, prio,
        w1, b1, g1, bt1, m1, v1,
        w2, b2, g2, bt2, m2, v2,
        w3, b3, wn, bnc,
        we1, be1, we2, be2, wei, bei, eidx);
    gather_kernel<<<1024, 256>>>(out);
}